// round 1
// baseline (speedup 1.0000x reference)
#include <cuda_runtime.h>
#include <math.h>
#include <stdint.h>

#define BB 8
#define NV 100
#define LQ 128
#define NKG 923
#define NT 1024
#define DV 2048
#define DK 300
#define DH 1024
#define NH 8
#define DHD 128
#define NLAYERS 3

// ---------------- scratch (device globals; no allocation allowed) ----------------
__device__ float g_vis[BB * NV * DH];
__device__ float g_pool[BB * DH];
__device__ float g_q[BB * DH];
__device__ float g_kg[BB * NKG * DH];
__device__ float g_x[BB * NT * DH];
__device__ float g_h[BB * NT * DH];
__device__ float g_s[BB * NT * NH];
__device__ float g_t[BB * NT * NH];
__device__ float g_e1s[BB * NT * NH];
__device__ float g_e2s[BB * NT * NH];
__device__ float g_e1t[BB * NT * NH];
__device__ float g_e2t[BB * NT * NH];
__device__ float g_ao[BB * NT * DH];
__device__ float g_scores[BB * NT];
__device__ float g_w[BB * NT];
__device__ float g_gvec[BB * DH];
__device__ float g_hid[BB * DH];

// ---------------- block reduce helpers (256 threads) ----------------
__device__ __forceinline__ float block_reduce_sum(float v) {
    __shared__ float sm[8];
    int lane = threadIdx.x & 31, w = threadIdx.x >> 5;
    #pragma unroll
    for (int o = 16; o > 0; o >>= 1) v += __shfl_down_sync(0xffffffffu, v, o);
    if (lane == 0) sm[w] = v;
    __syncthreads();
    if (threadIdx.x == 0) {
        float t = 0.f;
        #pragma unroll
        for (int i = 0; i < 8; i++) t += sm[i];
        sm[0] = t;
    }
    __syncthreads();
    float total = sm[0];
    __syncthreads();
    return total;
}

__device__ __forceinline__ float block_reduce_max(float v) {
    __shared__ float sm[8];
    int lane = threadIdx.x & 31, w = threadIdx.x >> 5;
    #pragma unroll
    for (int o = 16; o > 0; o >>= 1) v = fmaxf(v, __shfl_down_sync(0xffffffffu, v, o));
    if (lane == 0) sm[w] = v;
    __syncthreads();
    if (threadIdx.x == 0) {
        float t = sm[0];
        #pragma unroll
        for (int i = 1; i < 8; i++) t = fmaxf(t, sm[i]);
        sm[0] = t;
    }
    __syncthreads();
    float total = sm[0];
    __syncthreads();
    return total;
}

// ---------------- generic tiled SGEMM: C[M,N] = A[M,K] @ B[K,N] + bias[N] ----------------
__global__ void sgemm_bias(const float* __restrict__ A, const float* __restrict__ Bm,
                           const float* __restrict__ bias, float* __restrict__ C,
                           int M, int N, int K)
{
    __shared__ float As[8][128];
    __shared__ float Bs[8][128];
    int tid = threadIdx.x;
    int row0 = blockIdx.y * 128;
    int col0 = blockIdx.x * 128;
    int tx = tid & 15, ty = tid >> 4;

    float acc[8][8];
    #pragma unroll
    for (int i = 0; i < 8; i++)
        #pragma unroll
        for (int j = 0; j < 8; j++) acc[i][j] = 0.f;

    for (int k0 = 0; k0 < K; k0 += 8) {
        // A tile 128x8 -> As[k][m]
        #pragma unroll
        for (int i = 0; i < 4; i++) {
            int idx = tid + i * 256;
            int r = idx >> 3, c = idx & 7;
            float v = 0.f;
            if (row0 + r < M && k0 + c < K) v = A[(size_t)(row0 + r) * K + k0 + c];
            As[c][r] = v;
        }
        // B tile 8x128 -> Bs[k][n]
        #pragma unroll
        for (int i = 0; i < 4; i++) {
            int idx = tid + i * 256;
            int kk = idx >> 7, c = idx & 127;
            float v = 0.f;
            if (k0 + kk < K && col0 + c < N) v = Bm[(size_t)(k0 + kk) * N + col0 + c];
            Bs[kk][c] = v;
        }
        __syncthreads();
        #pragma unroll
        for (int kk = 0; kk < 8; kk++) {
            float a[8], b[8];
            #pragma unroll
            for (int i = 0; i < 8; i++) a[i] = As[kk][ty * 8 + i];
            #pragma unroll
            for (int j = 0; j < 8; j++) b[j] = Bs[kk][tx * 8 + j];
            #pragma unroll
            for (int i = 0; i < 8; i++)
                #pragma unroll
                for (int j = 0; j < 8; j++)
                    acc[i][j] += a[i] * b[j];
        }
        __syncthreads();
    }
    #pragma unroll
    for (int i = 0; i < 8; i++) {
        int r = row0 + ty * 8 + i;
        if (r >= M) continue;
        #pragma unroll
        for (int j = 0; j < 8; j++) {
            int c = col0 + tx * 8 + j;
            if (c < N) C[(size_t)r * N + c] = acc[i][j] + bias[c];
        }
    }
}

// ---------------- LayerNorm in-place over rows of length DH; grid = rows ----------------
__global__ void ln_rows(float* __restrict__ X, const float* __restrict__ g,
                        const float* __restrict__ b)
{
    int r = blockIdx.x;
    float4* xr = (float4*)(X + (size_t)r * DH);
    float4 v = xr[threadIdx.x];
    float sum = block_reduce_sum(v.x + v.y + v.z + v.w);
    float mean = sum * (1.f / DH);
    float dx = v.x - mean, dy = v.y - mean, dz = v.z - mean, dw = v.w - mean;
    float sq = block_reduce_sum(dx * dx + dy * dy + dz * dz + dw * dw);
    float inv = rsqrtf(sq * (1.f / DH) + 1e-5f);
    float4 gg = ((const float4*)g)[threadIdx.x];
    float4 bv = ((const float4*)b)[threadIdx.x];
    v.x = dx * inv * gg.x + bv.x;
    v.y = dy * inv * gg.y + bv.y;
    v.z = dz * inv * gg.z + bv.z;
    v.w = dw * inv * gg.w + bv.w;
    xr[threadIdx.x] = v;
}

// ---------------- residual + LN: x = LN(x + ao); grid = B*NT rows ----------------
__global__ void resid_ln(const float* __restrict__ g, const float* __restrict__ b)
{
    int r = blockIdx.x;
    float4* xr = (float4*)(g_x + (size_t)r * DH);
    const float4* ar = (const float4*)(g_ao + (size_t)r * DH);
    float4 v = xr[threadIdx.x];
    float4 a = ar[threadIdx.x];
    v.x += a.x; v.y += a.y; v.z += a.z; v.w += a.w;
    float sum = block_reduce_sum(v.x + v.y + v.z + v.w);
    float mean = sum * (1.f / DH);
    float dx = v.x - mean, dy = v.y - mean, dz = v.z - mean, dw = v.w - mean;
    float sq = block_reduce_sum(dx * dx + dy * dy + dz * dz + dw * dw);
    float inv = rsqrtf(sq * (1.f / DH) + 1e-5f);
    float4 gg = ((const float4*)g)[threadIdx.x];
    float4 bv = ((const float4*)b)[threadIdx.x];
    v.x = dx * inv * gg.x + bv.x;
    v.y = dy * inv * gg.y + bv.y;
    v.z = dz * inv * gg.z + bv.z;
    v.w = dw * inv * gg.w + bv.w;
    xr[threadIdx.x] = v;
}

// ---------------- text masked mean pool; grid (DH/128, B), block 128 ----------------
__global__ void text_pool(const int* __restrict__ ids, const int* __restrict__ mask,
                          const float* __restrict__ emb)
{
    int b = blockIdx.y;
    int d = blockIdx.x * 128 + threadIdx.x;
    float acc = 0.f, cnt = 0.f;
    for (int l = 0; l < LQ; l++) {
        float m = (float)mask[b * LQ + l];
        int id = ids[b * LQ + l];
        acc += m * emb[(size_t)id * DH + d];
        cnt += m;
    }
    g_pool[b * DH + d] = acc / fmaxf(cnt, 1.f);
}

// ---------------- small MM for tiny M: C[m,j] = act(sum_k A[m,k]B[k,j]+bias[j]) ----------------
__global__ void small_mm(const float* __restrict__ A, const float* __restrict__ Bm,
                         const float* __restrict__ bias, float* __restrict__ C,
                         int N, int K, int dogelu)
{
    int m = blockIdx.y;
    int j = blockIdx.x * blockDim.x + threadIdx.x;
    const float* a = A + (size_t)m * K;
    float acc0 = 0.f, acc1 = 0.f, acc2 = 0.f, acc3 = 0.f;
    for (int k = 0; k < K; k += 4) {
        acc0 += a[k + 0] * Bm[(size_t)(k + 0) * N + j];
        acc1 += a[k + 1] * Bm[(size_t)(k + 1) * N + j];
        acc2 += a[k + 2] * Bm[(size_t)(k + 2) * N + j];
        acc3 += a[k + 3] * Bm[(size_t)(k + 3) * N + j];
    }
    float acc = (acc0 + acc1) + (acc2 + acc3) + bias[j];
    if (dogelu) {
        float x = acc;
        acc = 0.5f * x * (1.f + tanhf(0.7978845608028654f * (x + 0.044715f * x * x * x)));
    }
    C[(size_t)m * N + j] = acc;
}

// ---------------- build x = concat(vis, q, kg) + type_emb[types]; grid (NT, B) ----------------
__global__ void pack_x(const int* __restrict__ types, const float* __restrict__ type_emb)
{
    int b = blockIdx.y, n = blockIdx.x;
    const float* src;
    if (n < NV)       src = g_vis + ((size_t)(b * NV + n)) * DH;
    else if (n == NV) src = g_q + (size_t)b * DH;
    else              src = g_kg + ((size_t)(b * NKG + (n - NV - 1))) * DH;
    int ty = types[b * NT + n];
    float4 v = ((const float4*)src)[threadIdx.x];
    float4 te = ((const float4*)(type_emb + (size_t)ty * DH))[threadIdx.x];
    v.x += te.x; v.y += te.y; v.z += te.z; v.w += te.w;
    ((float4*)(g_x + ((size_t)(b * NT + n)) * DH))[threadIdx.x] = v;
}

// ---------------- per-node s/t attention terms + factored exponentials ----------------
// grid (NT, B), block 256 (8 warps = 8 heads)
__global__ void st_kernel(const float* __restrict__ a_src, const float* __restrict__ a_dst)
{
    int b = blockIdx.y, n = blockIdx.x;
    int h = threadIdx.x >> 5, lane = threadIdx.x & 31;
    const float4* hr = (const float4*)(g_h + ((size_t)(b * NT + n)) * DH + h * DHD);
    const float4* as = (const float4*)(a_src + h * DHD);
    const float4* ad = (const float4*)(a_dst + h * DHD);
    float4 hv = hr[lane];
    float4 av = as[lane];
    float4 dv = ad[lane];
    float s = hv.x * av.x + hv.y * av.y + hv.z * av.z + hv.w * av.w;
    float t = hv.x * dv.x + hv.y * dv.y + hv.z * dv.z + hv.w * dv.w;
    #pragma unroll
    for (int o = 16; o > 0; o >>= 1) {
        s += __shfl_down_sync(0xffffffffu, s, o);
        t += __shfl_down_sync(0xffffffffu, t, o);
    }
    if (lane == 0) {
        int idx = (b * NT + n) * NH + h;
        g_s[idx] = s;
        g_t[idx] = t;
        g_e1s[idx] = __expf(s);
        g_e2s[idx] = __expf(0.2f * s);
        g_e1t[idx] = __expf(t);
        g_e2t[idx] = __expf(0.2f * t);
    }
}

// ---------------- fused GAT attention + aggregation ----------------
// grid (NT/32, NH, B), block 256. Thread: ii = tid>>3, d-chunk = (tid&7)*16.
__global__ void gat_attn(const int* __restrict__ adj)
{
    int b = blockIdx.z, h = blockIdx.y, i0 = blockIdx.x * 32;
    int tid = threadIdx.x;
    int ii = tid >> 3;        // 0..31 (i row in block)
    int jq = tid & 7;         // 0..7  (j quartet / d chunk)

    __shared__ float t_s[32], e1j_s[32], e2j_s[32];
    __shared__ float p_s[32][33];
    __shared__ float hs[32][128];
    __shared__ float rs_s[32][8];

    int irow = i0 + ii;
    int sidx = (b * NT + irow) * NH + h;
    float s_i = g_s[sidx];
    float e1i = g_e1s[sidx];
    float e2i = g_e2s[sidx];

    float acc[16];
    #pragma unroll
    for (int d = 0; d < 16; d++) acc[d] = 0.f;
    float rowsum = 0.f;

    const int* adjrow = adj + ((size_t)(b * NT + irow)) * NT;

    for (int j0 = 0; j0 < NT; j0 += 32) {
        __syncthreads();  // previous tile fully consumed
        if (tid < 32) {
            int tix = (b * NT + j0 + tid) * NH + h;
            t_s[tid] = g_t[tix];
            e1j_s[tid] = g_e1t[tix];
            e2j_s[tid] = g_e2t[tix];
        }
        #pragma unroll
        for (int i = 0; i < 4; i++) {
            int f = tid + i * 256;
            int jj = f >> 5, c4 = f & 31;
            ((float4*)hs[jj])[c4] =
                ((const float4*)(g_h + ((size_t)(b * NT + j0 + jj)) * DH + h * DHD))[c4];
        }
        __syncthreads();

        // scores for 4 j's
        int4 am = *(const int4*)(adjrow + j0 + jq * 4);
        {
            int jj = jq * 4;
            float u, p;
            u = s_i + t_s[jj + 0];
            p = (am.x > 0) ? (u > 0.f ? e1i * e1j_s[jj + 0] : e2i * e2j_s[jj + 0]) : 0.f;
            p_s[ii][jj + 0] = p; rowsum += p;
            u = s_i + t_s[jj + 1];
            p = (am.y > 0) ? (u > 0.f ? e1i * e1j_s[jj + 1] : e2i * e2j_s[jj + 1]) : 0.f;
            p_s[ii][jj + 1] = p; rowsum += p;
            u = s_i + t_s[jj + 2];
            p = (am.z > 0) ? (u > 0.f ? e1i * e1j_s[jj + 2] : e2i * e2j_s[jj + 2]) : 0.f;
            p_s[ii][jj + 2] = p; rowsum += p;
            u = s_i + t_s[jj + 3];
            p = (am.w > 0) ? (u > 0.f ? e1i * e1j_s[jj + 3] : e2i * e2j_s[jj + 3]) : 0.f;
            p_s[ii][jj + 3] = p; rowsum += p;
        }
        __syncthreads();

        // accumulate out[ii][dchunk] += p[ii][jj] * h[jj][dchunk]
        #pragma unroll 8
        for (int jj = 0; jj < 32; jj++) {
            float pv = p_s[ii][jj];
            float4 h0 = ((float4*)hs[jj])[jq * 4 + 0];
            float4 h1 = ((float4*)hs[jj])[jq * 4 + 1];
            float4 h2 = ((float4*)hs[jj])[jq * 4 + 2];
            float4 h3 = ((float4*)hs[jj])[jq * 4 + 3];
            acc[0]  += pv * h0.x; acc[1]  += pv * h0.y; acc[2]  += pv * h0.z; acc[3]  += pv * h0.w;
            acc[4]  += pv * h1.x; acc[5]  += pv * h1.y; acc[6]  += pv * h1.z; acc[7]  += pv * h1.w;
            acc[8]  += pv * h2.x; acc[9]  += pv * h2.y; acc[10] += pv * h2.z; acc[11] += pv * h2.w;
            acc[12] += pv * h3.x; acc[13] += pv * h3.y; acc[14] += pv * h3.z; acc[15] += pv * h3.w;
        }
    }

    // total rowsum per ii
    rs_s[ii][jq] = rowsum;
    __syncthreads();
    float total = 0.f;
    #pragma unroll
    for (int q = 0; q < 8; q++) total += rs_s[ii][q];
    float inv = (total > 0.f) ? (1.f / total) : 0.f;

    float* op = g_ao + ((size_t)(b * NT + irow)) * DH + h * DHD + jq * 16;
    #pragma unroll
    for (int v = 0; v < 4; v++) {
        float4 o;
        o.x = acc[v * 4 + 0] * inv;
        o.y = acc[v * 4 + 1] * inv;
        o.z = acc[v * 4 + 2] * inv;
        o.w = acc[v * 4 + 3] * inv;
        ((float4*)op)[v] = o;
    }
}

// ---------------- readout ----------------
// grid (NT/8, B), block 256: one warp per node
__global__ void readout_scores(const float* __restrict__ rW, const float* __restrict__ rb)
{
    int b = blockIdx.y;
    int n = blockIdx.x * 8 + (threadIdx.x >> 5);
    int lane = threadIdx.x & 31;
    const float* xr = g_x + ((size_t)(b * NT + n)) * DH;
    float acc = 0.f;
    #pragma unroll 8
    for (int k = lane; k < DH; k += 32) acc += xr[k] * rW[k];
    #pragma unroll
    for (int o = 16; o > 0; o >>= 1) acc += __shfl_down_sync(0xffffffffu, acc, o);
    if (lane == 0) g_scores[b * NT + n] = acc + rb[0];
}

// grid B, block 256
__global__ void softmax_nodes()
{
    int b = blockIdx.x;
    float4 s = ((const float4*)(g_scores + b * NT))[threadIdx.x];
    float mx = fmaxf(fmaxf(s.x, s.y), fmaxf(s.z, s.w));
    mx = block_reduce_max(mx);
    float e0 = __expf(s.x - mx), e1 = __expf(s.y - mx), e2 = __expf(s.z - mx), e3 = __expf(s.w - mx);
    float sum = block_reduce_sum(e0 + e1 + e2 + e3);
    float inv = 1.f / sum;
    float4 o; o.x = e0 * inv; o.y = e1 * inv; o.z = e2 * inv; o.w = e3 * inv;
    ((float4*)(g_w + b * NT))[threadIdx.x] = o;
}

// grid (DH/256, B), block 256
__global__ void weighted_sum()
{
    int b = blockIdx.y;
    int d = blockIdx.x * 256 + threadIdx.x;
    const float* w = g_w + b * NT;
    const float* x = g_x + (size_t)b * NT * DH + d;
    float a0 = 0.f, a1 = 0.f, a2 = 0.f, a3 = 0.f;
    for (int n = 0; n < NT; n += 4) {
        a0 += w[n + 0] * x[(size_t)(n + 0) * DH];
        a1 += w[n + 1] * x[(size_t)(n + 1) * DH];
        a2 += w[n + 2] * x[(size_t)(n + 2) * DH];
        a3 += w[n + 3] * x[(size_t)(n + 3) * DH];
    }
    g_gvec[b * DH + d] = (a0 + a1) + (a2 + a3);
}

// grid B, block 256
__global__ void final_logit(const float* __restrict__ W2, const float* __restrict__ b2,
                            float* __restrict__ out)
{
    int b = blockIdx.x;
    float4 h = ((const float4*)(g_hid + (size_t)b * DH))[threadIdx.x];
    float4 w = ((const float4*)W2)[threadIdx.x];
    float total = block_reduce_sum(h.x * w.x + h.y * w.y + h.z * w.z + h.w * w.w);
    if (threadIdx.x == 0) out[b] = total + b2[0];
}

// ---------------- launch ----------------
extern "C" void kernel_launch(void* const* d_in, const int* in_sizes, int n_in,
                              void* d_out, int out_size)
{
    const float* visual   = (const float*)d_in[0];
    const int*   qids     = (const int*)d_in[1];
    const int*   qmask    = (const int*)d_in[2];
    const float* kgf      = (const float*)d_in[3];
    const int*   adj      = (const int*)d_in[4];
    const int*   ntypes   = (const int*)d_in[5];
    const float* vis_W    = (const float*)d_in[6];
    const float* vis_b    = (const float*)d_in[7];
    const float* vis_ln_g = (const float*)d_in[8];
    const float* vis_ln_b = (const float*)d_in[9];
    const float* tok_emb  = (const float*)d_in[10];
    const float* q_W      = (const float*)d_in[11];
    const float* q_b      = (const float*)d_in[12];
    const float* q_ln_g   = (const float*)d_in[13];
    const float* q_ln_b   = (const float*)d_in[14];
    const float* kg_W     = (const float*)d_in[15];
    const float* kg_b     = (const float*)d_in[16];
    const float* kg_ln_g  = (const float*)d_in[17];
    const float* kg_ln_b  = (const float*)d_in[18];
    const float* type_emb = (const float*)d_in[19];
    const float* gat_W    = (const float*)d_in[20];
    const float* gat_b    = (const float*)d_in[21];
    const float* a_src    = (const float*)d_in[22];
    const float* a_dst    = (const float*)d_in[23];
    const float* gat_ln_g = (const float*)d_in[24];
    const float* gat_ln_b = (const float*)d_in[25];
    const float* rW       = (const float*)d_in[26];
    const float* rb       = (const float*)d_in[27];
    const float* cs_W1    = (const float*)d_in[28];
    const float* cs_b1    = (const float*)d_in[29];
    const float* cs_W2    = (const float*)d_in[30];
    const float* cs_b2    = (const float*)d_in[31];
    float* out = (float*)d_out;

    float *p_vis, *p_pool, *p_q, *p_kg, *p_x, *p_h, *p_g, *p_hid;
    cudaGetSymbolAddress((void**)&p_vis,  g_vis);
    cudaGetSymbolAddress((void**)&p_pool, g_pool);
    cudaGetSymbolAddress((void**)&p_q,    g_q);
    cudaGetSymbolAddress((void**)&p_kg,   g_kg);
    cudaGetSymbolAddress((void**)&p_x,    g_x);
    cudaGetSymbolAddress((void**)&p_h,    g_h);
    cudaGetSymbolAddress((void**)&p_g,    g_gvec);
    cudaGetSymbolAddress((void**)&p_hid,  g_hid);

    // 1. visual projection + LN
    sgemm_bias<<<dim3(DH / 128, (BB * NV + 127) / 128), 256>>>(visual, vis_W, vis_b, p_vis,
                                                               BB * NV, DH, DV);
    ln_rows<<<BB * NV, 256>>>(p_vis, vis_ln_g, vis_ln_b);

    // 2. text: pool -> proj -> LN
    text_pool<<<dim3(DH / 128, BB), 128>>>(qids, qmask, tok_emb);
    small_mm<<<dim3(DH / 256, BB), 256>>>(p_pool, q_W, q_b, p_q, DH, DH, 0);
    ln_rows<<<BB, 256>>>(p_q, q_ln_g, q_ln_b);

    // 3. KG projection + LN
    sgemm_bias<<<dim3(DH / 128, (BB * NKG + 127) / 128), 256>>>(kgf, kg_W, kg_b, p_kg,
                                                                BB * NKG, DH, DK);
    ln_rows<<<BB * NKG, 256>>>(p_kg, kg_ln_g, kg_ln_b);

    // 4-5. concat + type embeddings
    pack_x<<<dim3(NT, BB), 256>>>(ntypes, type_emb);

    // 6. GAT stack
    for (int l = 0; l < NLAYERS; l++) {
        sgemm_bias<<<dim3(DH / 128, (BB * NT) / 128), 256>>>(p_x, gat_W + (size_t)l * DH * DH,
                                                             gat_b + l * DH, p_h,
                                                             BB * NT, DH, DH);
        st_kernel<<<dim3(NT, BB), 256>>>(a_src + l * NH * DHD, a_dst + l * NH * DHD);
        gat_attn<<<dim3(NT / 32, NH, BB), 256>>>(adj);
        resid_ln<<<BB * NT, 256>>>(gat_ln_g + l * DH, gat_ln_b + l * DH);
    }

    // 7. attention-pooled readout
    readout_scores<<<dim3(NT / 8, BB), 256>>>(rW, rb);
    softmax_nodes<<<BB, 256>>>();
    weighted_sum<<<dim3(DH / 256, BB), 256>>>();

    // 8. candidate scorer
    small_mm<<<dim3(DH / 256, BB), 256>>>(p_g, cs_W1, cs_b1, p_hid, DH, DH, 1);
    final_logit<<<BB, 256>>>(cs_W2, cs_b2, out);
}

// round 4
// speedup vs baseline: 14.2346x; 14.2346x over previous
#include <cuda_runtime.h>
#include <math.h>
#include <stdint.h>

#define BB 8
#define NV 100
#define LQ 128
#define NKG 923
#define NT 1024
#define DV 2048
#define DK 300
#define DH 1024
#define NH 8
#define DHD 128
#define NLAYERS 3

#define SA 20     // As smem stride (u32): %32==4 -> fragment banks all distinct
#define SB 136    // Bs smem stride (u32): %32==8 -> fragment banks all distinct
#define PS_STRIDE 36
#define HS_STRIDE 136

// ---------------- scratch (device globals; no allocation allowed) ----------------
__device__ __align__(16) float g_vis[BB * NV * DH];
__device__ __align__(16) float g_pool[BB * DH];
__device__ __align__(16) float g_q[BB * DH];
__device__ __align__(16) float g_kg[BB * NKG * DH];
__device__ __align__(16) float g_x[BB * NT * DH];
__device__ __align__(16) float g_h[BB * NT * DH];
__device__ __align__(16) float g_s[BB * NT * NH];
__device__ __align__(16) float g_t[BB * NT * NH];
__device__ __align__(16) float g_e1s[BB * NT * NH];
__device__ __align__(16) float g_e2s[BB * NT * NH];
__device__ __align__(16) float g_e1t[BB * NT * NH];
__device__ __align__(16) float g_e2t[BB * NT * NH];
__device__ __align__(16) float g_ao[BB * NT * DH];
__device__ __align__(16) float g_scores[BB * NT];
__device__ __align__(16) float g_w[BB * NT];
__device__ __align__(16) float g_gvec[BB * DH];
__device__ __align__(16) float g_hid[BB * DH];

// ---------------- helpers ----------------
__device__ __forceinline__ uint32_t f2t(float f) {
    uint32_t u;
    asm("cvt.rna.tf32.f32 %0, %1;" : "=r"(u) : "f"(f));
    return u;
}

__device__ __forceinline__ void mma_tf32(float* d, const uint32_t* a, const uint32_t* b) {
    asm volatile(
        "mma.sync.aligned.m16n8k8.row.col.f32.tf32.tf32.f32 "
        "{%0,%1,%2,%3}, {%4,%5,%6,%7}, {%8,%9}, {%0,%1,%2,%3};"
        : "+f"(d[0]), "+f"(d[1]), "+f"(d[2]), "+f"(d[3])
        : "r"(a[0]), "r"(a[1]), "r"(a[2]), "r"(a[3]), "r"(b[0]), "r"(b[1]));
}

__device__ __forceinline__ float gelu_f(float x) {
    return 0.5f * x * (1.f + tanhf(0.7978845608028654f * (x + 0.044715f * x * x * x)));
}

__device__ __forceinline__ float block_reduce_sum(float v) {
    __shared__ float sm[8];
    int lane = threadIdx.x & 31, w = threadIdx.x >> 5;
    #pragma unroll
    for (int o = 16; o > 0; o >>= 1) v += __shfl_down_sync(0xffffffffu, v, o);
    if (lane == 0) sm[w] = v;
    __syncthreads();
    if (threadIdx.x == 0) {
        float t = 0.f;
        #pragma unroll
        for (int i = 0; i < 8; i++) t += sm[i];
        sm[0] = t;
    }
    __syncthreads();
    float total = sm[0];
    __syncthreads();
    return total;
}

__device__ __forceinline__ float block_reduce_max(float v) {
    __shared__ float sm[8];
    int lane = threadIdx.x & 31, w = threadIdx.x >> 5;
    #pragma unroll
    for (int o = 16; o > 0; o >>= 1) v = fmaxf(v, __shfl_down_sync(0xffffffffu, v, o));
    if (lane == 0) sm[w] = v;
    __syncthreads();
    if (threadIdx.x == 0) {
        float t = sm[0];
        #pragma unroll
        for (int i = 1; i < 8; i++) t = fmaxf(t, sm[i]);
        sm[0] = t;
    }
    __syncthreads();
    float total = sm[0];
    __syncthreads();
    return total;
}

// ---------------- tf32 tensor-core GEMM: C[M,N] = A[M,K]@B[K,N] + bias, opt gelu -------
// 256 threads, block tile 128x128, BK=16, warp tile 64x32 (warps 2x4).
__device__ __forceinline__ void mg_load(const float* __restrict__ A, const float* __restrict__ B,
                                        int M, int N, int K, int m0b, int n0b, int kt,
                                        int ar, int ac, int br, int bc,
                                        float4* av, float4* bv)
{
    int k0 = kt * 16;
    #pragma unroll
    for (int i = 0; i < 2; i++) {
        int r = m0b + ar + i * 64;
        float4 v = make_float4(0.f, 0.f, 0.f, 0.f);
        if (r < M) {
            if (k0 + 16 <= K) {
                v = *(const float4*)(A + (size_t)r * K + k0 + ac);
            } else {
                float e0 = (k0 + ac + 0 < K) ? A[(size_t)r * K + k0 + ac + 0] : 0.f;
                float e1 = (k0 + ac + 1 < K) ? A[(size_t)r * K + k0 + ac + 1] : 0.f;
                float e2 = (k0 + ac + 2 < K) ? A[(size_t)r * K + k0 + ac + 2] : 0.f;
                float e3 = (k0 + ac + 3 < K) ? A[(size_t)r * K + k0 + ac + 3] : 0.f;
                v = make_float4(e0, e1, e2, e3);
            }
        }
        av[i] = v;
    }
    #pragma unroll
    for (int i = 0; i < 2; i++) {
        int kr = k0 + br + i * 8;
        float4 v = make_float4(0.f, 0.f, 0.f, 0.f);
        if (kr < K) v = *(const float4*)(B + (size_t)kr * N + n0b + bc);
        bv[i] = v;
    }
}

__device__ __forceinline__ void mg_store(uint32_t* As, uint32_t* Bs,
                                         int ar, int ac, int br, int bc,
                                         const float4* av, const float4* bv)
{
    #pragma unroll
    for (int i = 0; i < 2; i++) {
        uint4 u;
        u.x = f2t(av[i].x); u.y = f2t(av[i].y); u.z = f2t(av[i].z); u.w = f2t(av[i].w);
        *(uint4*)(As + (ar + i * 64) * SA + ac) = u;
        uint4 w;
        w.x = f2t(bv[i].x); w.y = f2t(bv[i].y); w.z = f2t(bv[i].z); w.w = f2t(bv[i].w);
        *(uint4*)(Bs + (br + i * 8) * SB + bc) = w;
    }
}

__global__ void __launch_bounds__(256, 2)
mma_gemm(const float* __restrict__ A, const float* __restrict__ B,
         const float* __restrict__ bias, float* __restrict__ C,
         int M, int N, int K, int act)
{
    __shared__ uint32_t As[128 * SA];
    __shared__ uint32_t Bs[16 * SB];
    int tid = threadIdx.x, warp = tid >> 5, lane = tid & 31;
    int grp = lane >> 2, qid = lane & 3;
    int m0b = blockIdx.y * 128, n0b = blockIdx.x * 128;
    int wm = warp >> 2, wn = warp & 3;
    int m0 = wm * 64, n0 = wn * 32;

    int ar = tid >> 2, ac = (tid & 3) * 4;   // A tile: rows ar, ar+64; k off ac
    int br = tid >> 5, bc = (tid & 31) * 4;  // B tile: k rows br, br+8; n off bc

    float acc[4][4][4];
    #pragma unroll
    for (int mt = 0; mt < 4; mt++)
        #pragma unroll
        for (int nt = 0; nt < 4; nt++)
            #pragma unroll
            for (int e = 0; e < 4; e++) acc[mt][nt][e] = 0.f;

    int ktiles = (K + 15) / 16;
    float4 av[2], bv[2];
    mg_load(A, B, M, N, K, m0b, n0b, 0, ar, ac, br, bc, av, bv);
    mg_store(As, Bs, ar, ac, br, bc, av, bv);
    __syncthreads();

    for (int kt = 0; kt < ktiles; kt++) {
        if (kt + 1 < ktiles)
            mg_load(A, B, M, N, K, m0b, n0b, kt + 1, ar, ac, br, bc, av, bv);

        #pragma unroll
        for (int kg = 0; kg < 2; kg++) {
            int kb = kg * 8 + qid;
            uint32_t af[4][4], bf[4][2];
            #pragma unroll
            for (int mt = 0; mt < 4; mt++) {
                int r = m0 + mt * 16 + grp;
                af[mt][0] = As[r * SA + kb];
                af[mt][1] = As[(r + 8) * SA + kb];
                af[mt][2] = As[r * SA + kb + 4];
                af[mt][3] = As[(r + 8) * SA + kb + 4];
            }
            #pragma unroll
            for (int nt = 0; nt < 4; nt++) {
                int c = n0 + nt * 8 + grp;
                bf[nt][0] = Bs[kb * SB + c];
                bf[nt][1] = Bs[(kb + 4) * SB + c];
            }
            #pragma unroll
            for (int mt = 0; mt < 4; mt++)
                #pragma unroll
                for (int nt = 0; nt < 4; nt++)
                    mma_tf32(acc[mt][nt], af[mt], bf[nt]);
        }
        __syncthreads();
        if (kt + 1 < ktiles) {
            mg_store(As, Bs, ar, ac, br, bc, av, bv);
            __syncthreads();
        }
    }

    #pragma unroll
    for (int mt = 0; mt < 4; mt++) {
        int r0 = m0b + m0 + mt * 16 + grp;
        #pragma unroll
        for (int nt = 0; nt < 4; nt++) {
            int c0 = n0b + n0 + nt * 8 + qid * 2;
            float b0v = bias[c0], b1v = bias[c0 + 1];
            if (r0 < M) {
                float o0 = acc[mt][nt][0] + b0v, o1 = acc[mt][nt][1] + b1v;
                if (act) { o0 = gelu_f(o0); o1 = gelu_f(o1); }
                float2 o; o.x = o0; o.y = o1;
                *(float2*)(C + (size_t)r0 * N + c0) = o;
            }
            if (r0 + 8 < M) {
                float o0 = acc[mt][nt][2] + b0v, o1 = acc[mt][nt][3] + b1v;
                if (act) { o0 = gelu_f(o0); o1 = gelu_f(o1); }
                float2 o; o.x = o0; o.y = o1;
                *(float2*)(C + (size_t)(r0 + 8) * N + c0) = o;
            }
        }
    }
}

// ---------------- LayerNorm in-place over rows of length DH; grid = rows ----------------
__global__ void ln_rows(float* __restrict__ X, const float* __restrict__ g,
                        const float* __restrict__ b)
{
    int r = blockIdx.x;
    float4* xr = (float4*)(X + (size_t)r * DH);
    float4 v = xr[threadIdx.x];
    float sum = block_reduce_sum(v.x + v.y + v.z + v.w);
    float mean = sum * (1.f / DH);
    float dx = v.x - mean, dy = v.y - mean, dz = v.z - mean, dw = v.w - mean;
    float sq = block_reduce_sum(dx * dx + dy * dy + dz * dz + dw * dw);
    float inv = rsqrtf(sq * (1.f / DH) + 1e-5f);
    float4 gg = ((const float4*)g)[threadIdx.x];
    float4 bv = ((const float4*)b)[threadIdx.x];
    v.x = dx * inv * gg.x + bv.x;
    v.y = dy * inv * gg.y + bv.y;
    v.z = dz * inv * gg.z + bv.z;
    v.w = dw * inv * gg.w + bv.w;
    xr[threadIdx.x] = v;
}

// ---------------- residual + LN: x = LN(x + ao); grid = B*NT rows ----------------
__global__ void resid_ln(const float* __restrict__ g, const float* __restrict__ b)
{
    int r = blockIdx.x;
    float4* xr = (float4*)(g_x + (size_t)r * DH);
    const float4* ar = (const float4*)(g_ao + (size_t)r * DH);
    float4 v = xr[threadIdx.x];
    float4 a = ar[threadIdx.x];
    v.x += a.x; v.y += a.y; v.z += a.z; v.w += a.w;
    float sum = block_reduce_sum(v.x + v.y + v.z + v.w);
    float mean = sum * (1.f / DH);
    float dx = v.x - mean, dy = v.y - mean, dz = v.z - mean, dw = v.w - mean;
    float sq = block_reduce_sum(dx * dx + dy * dy + dz * dz + dw * dw);
    float inv = rsqrtf(sq * (1.f / DH) + 1e-5f);
    float4 gg = ((const float4*)g)[threadIdx.x];
    float4 bv = ((const float4*)b)[threadIdx.x];
    v.x = dx * inv * gg.x + bv.x;
    v.y = dy * inv * gg.y + bv.y;
    v.z = dz * inv * gg.z + bv.z;
    v.w = dw * inv * gg.w + bv.w;
    xr[threadIdx.x] = v;
}

// ---------------- text masked mean pool; grid (DH/128, B), block 128 ----------------
__global__ void text_pool(const int* __restrict__ ids, const int* __restrict__ mask,
                          const float* __restrict__ emb)
{
    int b = blockIdx.y;
    int d = blockIdx.x * 128 + threadIdx.x;
    float acc = 0.f, cnt = 0.f;
    for (int l = 0; l < LQ; l++) {
        float m = (float)mask[b * LQ + l];
        int id = ids[b * LQ + l];
        acc += m * emb[(size_t)id * DH + d];
        cnt += m;
    }
    g_pool[b * DH + d] = acc / fmaxf(cnt, 1.f);
}

// ---------------- build x = concat(vis, q, kg) + type_emb[types]; grid (NT, B) ----------
__global__ void pack_x(const int* __restrict__ types, const float* __restrict__ type_emb)
{
    int b = blockIdx.y, n = blockIdx.x;
    const float* src;
    if (n < NV)       src = g_vis + ((size_t)(b * NV + n)) * DH;
    else if (n == NV) src = g_q + (size_t)b * DH;
    else              src = g_kg + ((size_t)(b * NKG + (n - NV - 1))) * DH;
    int ty = types[b * NT + n];
    float4 v = ((const float4*)src)[threadIdx.x];
    float4 te = ((const float4*)(type_emb + (size_t)ty * DH))[threadIdx.x];
    v.x += te.x; v.y += te.y; v.z += te.z; v.w += te.w;
    ((float4*)(g_x + ((size_t)(b * NT + n)) * DH))[threadIdx.x] = v;
}

// ---------------- per-node s/t attention terms + factored exponentials ----------------
// grid (NT, B), block 256 (8 warps = 8 heads)
__global__ void st_kernel(const float* __restrict__ a_src, const float* __restrict__ a_dst)
{
    int b = blockIdx.y, n = blockIdx.x;
    int h = threadIdx.x >> 5, lane = threadIdx.x & 31;
    const float4* hr = (const float4*)(g_h + ((size_t)(b * NT + n)) * DH + h * DHD);
    const float4* as = (const float4*)(a_src + h * DHD);
    const float4* ad = (const float4*)(a_dst + h * DHD);
    float4 hv = hr[lane];
    float4 av = as[lane];
    float4 dv = ad[lane];
    float s = hv.x * av.x + hv.y * av.y + hv.z * av.z + hv.w * av.w;
    float t = hv.x * dv.x + hv.y * dv.y + hv.z * dv.z + hv.w * dv.w;
    #pragma unroll
    for (int o = 16; o > 0; o >>= 1) {
        s += __shfl_down_sync(0xffffffffu, s, o);
        t += __shfl_down_sync(0xffffffffu, t, o);
    }
    if (lane == 0) {
        int idx = (b * NT + n) * NH + h;
        g_s[idx] = s;
        g_t[idx] = t;
        g_e1s[idx] = __expf(s);
        g_e2s[idx] = __expf(0.2f * s);
        g_e1t[idx] = __expf(t);
        g_e2t[idx] = __expf(0.2f * t);
    }
}

// ---------------- fused GAT attention + aggregation via tf32 MMA ----------------
// grid (NT/128, NH, B), block 256. out[128 x 128] = normalize(P) @ H.
// dyn smem layout (u32 units): Ps[128*36] | Hs[32*136] | tall[1024] | e1all[1024]
//                              | e2all[1024] | rs2[256] | invs[128]
#define GAT_SMEM_U32 (128 * PS_STRIDE + 32 * HS_STRIDE + 3 * 1024 + 256 + 128)

__global__ void __launch_bounds__(256, 2)
gat_attn_mma(const int* __restrict__ adj)
{
    extern __shared__ uint32_t dyn[];
    uint32_t* Ps = dyn;
    uint32_t* Hs = dyn + 128 * PS_STRIDE;
    float* tall  = (float*)(Hs + 32 * HS_STRIDE);
    float* e1all = tall + 1024;
    float* e2all = e1all + 1024;
    float* rs2   = e2all + 1024;
    float* invs  = rs2 + 256;

    int b = blockIdx.z, h = blockIdx.y, i0 = blockIdx.x * 128;
    int tid = threadIdx.x, warp = tid >> 5, lane = tid & 31;
    int grp = lane >> 2, qid = lane & 3;
    int wm = warp >> 2, wn = warp & 3;
    int m0 = wm * 64, n0 = wn * 32;
    int pi = tid >> 1, jh = (tid & 1) * 16;

    // preload t / e1t / e2t for all 1024 neighbors of this (b,h)
    #pragma unroll
    for (int it = 0; it < 4; it++) {
        int n = tid + it * 256;
        int ix = (b * NT + n) * NH + h;
        tall[n]  = g_t[ix];
        e1all[n] = g_e1t[ix];
        e2all[n] = g_e2t[ix];
    }
    int sidx = (b * NT + i0 + pi) * NH + h;
    float s_i = g_s[sidx], e1i = g_e1s[sidx], e2i = g_e2s[sidx];

    float acc[4][4][4];
    #pragma unroll
    for (int mt = 0; mt < 4; mt++)
        #pragma unroll
        for (int nt = 0; nt < 4; nt++)
            #pragma unroll
            for (int e = 0; e < 4; e++) acc[mt][nt][e] = 0.f;
    float rsum = 0.f;

    const int* arow = adj + (size_t)(b * NT + i0 + pi) * NT;
    __syncthreads();  // tall/e1all/e2all ready

    for (int j0 = 0; j0 < NT; j0 += 32) {
        // issue global loads into registers (latency overlaps previous-tile MMA)
        float4 hv[4];
        #pragma unroll
        for (int it = 0; it < 4; it++) {
            int f = tid + it * 256;
            int r = f >> 5, c4 = f & 31;
            hv[it] = *(const float4*)(g_h + ((size_t)(b * NT + j0 + r)) * DH + h * DHD + c4 * 4);
        }
        int4 am[4];
        #pragma unroll
        for (int q = 0; q < 4; q++) am[q] = *(const int4*)(arow + j0 + jh + q * 4);

        __syncthreads();  // previous MMA done reading Ps/Hs

        // store H tile (tf32)
        #pragma unroll
        for (int it = 0; it < 4; it++) {
            int f = tid + it * 256;
            int r = f >> 5, c4 = f & 31;
            uint4 u;
            u.x = f2t(hv[it].x); u.y = f2t(hv[it].y); u.z = f2t(hv[it].z); u.w = f2t(hv[it].w);
            *(uint4*)(Hs + r * HS_STRIDE + c4 * 4) = u;
        }
        // compute P tile entries (factored exp trick) + rowsum, store tf32
        #pragma unroll
        for (int q = 0; q < 4; q++) {
            int mk[4] = { am[q].x, am[q].y, am[q].z, am[q].w };
            uint4 pu;
            uint32_t* pp = (uint32_t*)&pu;
            #pragma unroll
            for (int e = 0; e < 4; e++) {
                int jj = j0 + jh + q * 4 + e;
                float u = s_i + tall[jj];
                float p = 0.f;
                if (mk[e] > 0) p = (u > 0.f) ? e1i * e1all[jj] : e2i * e2all[jj];
                uint32_t pb = f2t(p);
                pp[e] = pb;
                rsum += __uint_as_float(pb);
            }
            *(uint4*)(Ps + pi * PS_STRIDE + jh + q * 4) = pu;
        }
        __syncthreads();

        // MMA: 4 k-groups of 8
        #pragma unroll
        for (int kg = 0; kg < 4; kg++) {
            int kb = kg * 8 + qid;
            uint32_t af[4][4], bf[4][2];
            #pragma unroll
            for (int mt = 0; mt < 4; mt++) {
                int r = m0 + mt * 16 + grp;
                af[mt][0] = Ps[r * PS_STRIDE + kb];
                af[mt][1] = Ps[(r + 8) * PS_STRIDE + kb];
                af[mt][2] = Ps[r * PS_STRIDE + kb + 4];
                af[mt][3] = Ps[(r + 8) * PS_STRIDE + kb + 4];
            }
            #pragma unroll
            for (int nt = 0; nt < 4; nt++) {
                int c = n0 + nt * 8 + grp;
                bf[nt][0] = Hs[kb * HS_STRIDE + c];
                bf[nt][1] = Hs[(kb + 4) * HS_STRIDE + c];
            }
            #pragma unroll
            for (int mt = 0; mt < 4; mt++)
                #pragma unroll
                for (int nt = 0; nt < 4; nt++)
                    mma_tf32(acc[mt][nt], af[mt], bf[nt]);
        }
    }

    rs2[pi * 2 + (tid & 1)] = rsum;
    __syncthreads();
    if (tid < 128) {
        float r = rs2[tid * 2] + rs2[tid * 2 + 1];
        invs[tid] = (r > 0.f) ? (1.f / r) : 0.f;
    }
    __syncthreads();

    #pragma unroll
    for (int mt = 0; mt < 4; mt++) {
        int rl = m0 + mt * 16 + grp;
        float iv0 = invs[rl], iv1 = invs[rl + 8];
        size_t base0 = ((size_t)(b * NT + i0 + rl)) * DH + h * DHD;
        size_t base1 = ((size_t)(b * NT + i0 + rl + 8)) * DH + h * DHD;
        #pragma unroll
        for (int nt = 0; nt < 4; nt++) {
            int c = n0 + nt * 8 + qid * 2;
            float2 o0; o0.x = acc[mt][nt][0] * iv0; o0.y = acc[mt][nt][1] * iv0;
            float2 o1; o1.x = acc[mt][nt][2] * iv1; o1.y = acc[mt][nt][3] * iv1;
            *(float2*)(g_ao + base0 + c) = o0;
            *(float2*)(g_ao + base1 + c) = o1;
        }
    }
}

// ---------------- readout ----------------
__global__ void readout_scores(const float* __restrict__ rW, const float* __restrict__ rb)
{
    int b = blockIdx.y;
    int n = blockIdx.x * 8 + (threadIdx.x >> 5);
    int lane = threadIdx.x & 31;
    const float* xr = g_x + ((size_t)(b * NT + n)) * DH;
    float acc = 0.f;
    #pragma unroll 8
    for (int k = lane; k < DH; k += 32) acc += xr[k] * rW[k];
    #pragma unroll
    for (int o = 16; o > 0; o >>= 1) acc += __shfl_down_sync(0xffffffffu, acc, o);
    if (lane == 0) g_scores[b * NT + n] = acc + rb[0];
}

__global__ void softmax_nodes()
{
    int b = blockIdx.x;
    float4 s = ((const float4*)(g_scores + b * NT))[threadIdx.x];
    float mx = fmaxf(fmaxf(s.x, s.y), fmaxf(s.z, s.w));
    mx = block_reduce_max(mx);
    float e0 = __expf(s.x - mx), e1 = __expf(s.y - mx), e2 = __expf(s.z - mx), e3 = __expf(s.w - mx);
    float sum = block_reduce_sum(e0 + e1 + e2 + e3);
    float inv = 1.f / sum;
    float4 o; o.x = e0 * inv; o.y = e1 * inv; o.z = e2 * inv; o.w = e3 * inv;
    ((float4*)(g_w + b * NT))[threadIdx.x] = o;
}

__global__ void weighted_sum()
{
    int b = blockIdx.y;
    int d = blockIdx.x * 256 + threadIdx.x;
    const float* w = g_w + b * NT;
    const float* x = g_x + (size_t)b * NT * DH + d;
    float a0 = 0.f, a1 = 0.f, a2 = 0.f, a3 = 0.f;
    for (int n = 0; n < NT; n += 4) {
        a0 += w[n + 0] * x[(size_t)(n + 0) * DH];
        a1 += w[n + 1] * x[(size_t)(n + 1) * DH];
        a2 += w[n + 2] * x[(size_t)(n + 2) * DH];
        a3 += w[n + 3] * x[(size_t)(n + 3) * DH];
    }
    g_gvec[b * DH + d] = (a0 + a1) + (a2 + a3);
}

__global__ void final_logit(const float* __restrict__ W2, const float* __restrict__ b2,
                            float* __restrict__ out)
{
    int b = blockIdx.x;
    float4 h = ((const float4*)(g_hid + (size_t)b * DH))[threadIdx.x];
    float4 w = ((const float4*)W2)[threadIdx.x];
    float total = block_reduce_sum(h.x * w.x + h.y * w.y + h.z * w.z + h.w * w.w);
    if (threadIdx.x == 0) out[b] = total + b2[0];
}

// ---------------- launch ----------------
extern "C" void kernel_launch(void* const* d_in, const int* in_sizes, int n_in,
                              void* d_out, int out_size)
{
    const float* visual   = (const float*)d_in[0];
    const int*   qids     = (const int*)d_in[1];
    const int*   qmask    = (const int*)d_in[2];
    const float* kgf      = (const float*)d_in[3];
    const int*   adj      = (const int*)d_in[4];
    const int*   ntypes   = (const int*)d_in[5];
    const float* vis_W    = (const float*)d_in[6];
    const float* vis_b    = (const float*)d_in[7];
    const float* vis_ln_g = (const float*)d_in[8];
    const float* vis_ln_b = (const float*)d_in[9];
    const float* tok_emb  = (const float*)d_in[10];
    const float* q_W      = (const float*)d_in[11];
    const float* q_b      = (const float*)d_in[12];
    const float* q_ln_g   = (const float*)d_in[13];
    const float* q_ln_b   = (const float*)d_in[14];
    const float* kg_W     = (const float*)d_in[15];
    const float* kg_b     = (const float*)d_in[16];
    const float* kg_ln_g  = (const float*)d_in[17];
    const float* kg_ln_b  = (const float*)d_in[18];
    const float* type_emb = (const float*)d_in[19];
    const float* gat_W    = (const float*)d_in[20];
    const float* gat_b    = (const float*)d_in[21];
    const float* a_src    = (const float*)d_in[22];
    const float* a_dst    = (const float*)d_in[23];
    const float* gat_ln_g = (const float*)d_in[24];
    const float* gat_ln_b = (const float*)d_in[25];
    const float* rW       = (const float*)d_in[26];
    const float* rb       = (const float*)d_in[27];
    const float* cs_W1    = (const float*)d_in[28];
    const float* cs_b1    = (const float*)d_in[29];
    const float* cs_W2    = (const float*)d_in[30];
    const float* cs_b2    = (const float*)d_in[31];
    float* out = (float*)d_out;

    float *p_vis, *p_pool, *p_q, *p_kg, *p_x, *p_h, *p_g, *p_hid;
    cudaGetSymbolAddress((void**)&p_vis,  g_vis);
    cudaGetSymbolAddress((void**)&p_pool, g_pool);
    cudaGetSymbolAddress((void**)&p_q,    g_q);
    cudaGetSymbolAddress((void**)&p_kg,   g_kg);
    cudaGetSymbolAddress((void**)&p_x,    g_x);
    cudaGetSymbolAddress((void**)&p_h,    g_h);
    cudaGetSymbolAddress((void**)&p_g,    g_gvec);
    cudaGetSymbolAddress((void**)&p_hid,  g_hid);

    const int GAT_SMEM_BYTES = GAT_SMEM_U32 * 4;  // 49664
    cudaFuncSetAttribute(gat_attn_mma, cudaFuncAttributeMaxDynamicSharedMemorySize,
                         GAT_SMEM_BYTES);

    // 1. visual projection + LN
    mma_gemm<<<dim3(DH / 128, (BB * NV + 127) / 128), 256>>>(visual, vis_W, vis_b, p_vis,
                                                             BB * NV, DH, DV, 0);
    ln_rows<<<BB * NV, 256>>>(p_vis, vis_ln_g, vis_ln_b);

    // 2. text: pool -> proj -> LN
    text_pool<<<dim3(DH / 128, BB), 128>>>(qids, qmask, tok_emb);
    mma_gemm<<<dim3(DH / 128, 1), 256>>>(p_pool, q_W, q_b, p_q, BB, DH, DH, 0);
    ln_rows<<<BB, 256>>>(p_q, q_ln_g, q_ln_b);

    // 3. KG projection + LN
    mma_gemm<<<dim3(DH / 128, (BB * NKG + 127) / 128), 256>>>(kgf, kg_W, kg_b, p_kg,
                                                              BB * NKG, DH, DK, 0);
    ln_rows<<<BB * NKG, 256>>>(p_kg, kg_ln_g, kg_ln_b);

    // 4-5. concat + type embeddings
    pack_x<<<dim3(NT, BB), 256>>>(ntypes, type_emb);

    // 6. GAT stack
    for (int l = 0; l < NLAYERS; l++) {
        mma_gemm<<<dim3(DH / 128, (BB * NT) / 128), 256>>>(p_x, gat_W + (size_t)l * DH * DH,
                                                           gat_b + l * DH, p_h,
                                                           BB * NT, DH, DH, 0);
        st_kernel<<<dim3(NT, BB), 256>>>(a_src + l * NH * DHD, a_dst + l * NH * DHD);
        gat_attn_mma<<<dim3(NT / 128, NH, BB), 256, GAT_SMEM_BYTES>>>(adj);
        resid_ln<<<BB * NT, 256>>>(gat_ln_g + l * DH, gat_ln_b + l * DH);
    }

    // 7. attention-pooled readout
    readout_scores<<<dim3(NT / 8, BB), 256>>>(rW, rb);
    softmax_nodes<<<BB, 256>>>();
    weighted_sum<<<dim3(DH / 256, BB), 256>>>();

    // 8. candidate scorer
    mma_gemm<<<dim3(DH / 128, 1), 256>>>(p_g, cs_W1, cs_b1, p_hid, BB, DH, DH, 1);
    final_logit<<<BB, 256>>>(cs_W2, cs_b2, out);
}

// round 5
// speedup vs baseline: 16.0846x; 1.1300x over previous
#include <cuda_runtime.h>
#include <math.h>
#include <stdint.h>

#define BB 8
#define NV 100
#define LQ 128
#define NKG 923
#define NT 1024
#define DV 2048
#define DK 300
#define DH 1024
#define NH 8
#define DHD 128
#define NLAYERS 3

#define SA 20     // As smem stride (u32)
#define SB 136    // Bs smem stride (u32)
#define PS_STRIDE 36
#define HS_STRIDE 136

#define GSTAGE (128 * SA + 16 * SB)          // u32 per gemm stage (4736)
#define GEMM_SMEM_BYTES (3 * GSTAGE * 4)     // 56832

// ---------------- scratch (device globals; no allocation allowed) ----------------
__device__ __align__(16) float g_vis[BB * NV * DH];
__device__ __align__(16) float g_pool[BB * DH];
__device__ __align__(16) float g_q[BB * DH];
__device__ __align__(16) float g_kg[BB * NKG * DH];
__device__ __align__(16) float g_x[BB * NT * DH];
__device__ __align__(16) float g_h[BB * NT * DH];
__device__ __align__(16) float g_s[BB * NT * NH];
__device__ __align__(16) float g_t[BB * NT * NH];
__device__ __align__(16) float g_e1s[BB * NT * NH];
__device__ __align__(16) float g_e2s[BB * NT * NH];
__device__ __align__(16) float g_e1t[BB * NT * NH];
__device__ __align__(16) float g_e2t[BB * NT * NH];
__device__ __align__(16) float g_ao[BB * NT * DH];
__device__ __align__(16) float g_scores[BB * NT];
__device__ __align__(16) float g_w[BB * NT];
__device__ __align__(16) float g_gvec[BB * DH];
__device__ __align__(16) float g_hid[BB * DH];
__device__ __align__(16) uint32_t g_adjbits[BB * NT * (NT / 32)];

// ---------------- helpers ----------------
__device__ __forceinline__ uint32_t f2t(float f) {
    uint32_t u;
    asm("cvt.rna.tf32.f32 %0, %1;" : "=r"(u) : "f"(f));
    return u;
}

__device__ __forceinline__ void mma_tf32(float* d, const uint32_t* a, const uint32_t* b) {
    asm volatile(
        "mma.sync.aligned.m16n8k8.row.col.f32.tf32.tf32.f32 "
        "{%0,%1,%2,%3}, {%4,%5,%6,%7}, {%8,%9}, {%0,%1,%2,%3};"
        : "+f"(d[0]), "+f"(d[1]), "+f"(d[2]), "+f"(d[3])
        : "r"(a[0]), "r"(a[1]), "r"(a[2]), "r"(a[3]), "r"(b[0]), "r"(b[1]));
}

__device__ __forceinline__ void cpa16(uint32_t dst, const void* src, int bytes) {
    asm volatile("cp.async.cg.shared.global [%0], [%1], 16, %2;"
                 :: "r"(dst), "l"(src), "r"(bytes));
}
#define CP_COMMIT() asm volatile("cp.async.commit_group;")
#define CP_WAIT(n)  asm volatile("cp.async.wait_group %0;" :: "n"(n))

__device__ __forceinline__ float gelu_f(float x) {
    return 0.5f * x * (1.f + tanhf(0.7978845608028654f * (x + 0.044715f * x * x * x)));
}

__device__ __forceinline__ float block_reduce_sum(float v) {
    __shared__ float sm[8];
    int lane = threadIdx.x & 31, w = threadIdx.x >> 5;
    #pragma unroll
    for (int o = 16; o > 0; o >>= 1) v += __shfl_down_sync(0xffffffffu, v, o);
    if (lane == 0) sm[w] = v;
    __syncthreads();
    if (threadIdx.x == 0) {
        float t = 0.f;
        #pragma unroll
        for (int i = 0; i < 8; i++) t += sm[i];
        sm[0] = t;
    }
    __syncthreads();
    float total = sm[0];
    __syncthreads();
    return total;
}

__device__ __forceinline__ float block_reduce_max(float v) {
    __shared__ float sm[8];
    int lane = threadIdx.x & 31, w = threadIdx.x >> 5;
    #pragma unroll
    for (int o = 16; o > 0; o >>= 1) v = fmaxf(v, __shfl_down_sync(0xffffffffu, v, o));
    if (lane == 0) sm[w] = v;
    __syncthreads();
    if (threadIdx.x == 0) {
        float t = sm[0];
        #pragma unroll
        for (int i = 1; i < 8; i++) t = fmaxf(t, sm[i]);
        sm[0] = t;
    }
    __syncthreads();
    float total = sm[0];
    __syncthreads();
    return total;
}

// ---------------- tf32 tensor-core GEMM, 3-stage cp.async pipeline ----------------
// 256 threads, block tile 128x128, BK=16, warp tile 64x32 (warps 2x4).
__device__ __forceinline__ void gm_issue(const float* __restrict__ A,
                                         const float* __restrict__ B,
                                         int M, int N, int K, int m0b, int n0b,
                                         int kt, uint32_t stage_addr,
                                         int ar, int ac, int br, int bc)
{
    int k0 = kt * 16;
    #pragma unroll
    for (int i = 0; i < 2; i++) {
        int r = m0b + ar + i * 64;
        int rr = (r < M) ? r : 0;
        int kc = k0 + ac;
        int rem4 = (K - kc) * 4;
        int bytes = (r < M) ? (rem4 > 16 ? 16 : (rem4 > 0 ? rem4 : 0)) : 0;
        int kcc = (kc < K) ? kc : 0;
        cpa16(stage_addr + (uint32_t)((ar + i * 64) * SA + ac) * 4,
              A + (size_t)rr * K + kcc, bytes);
    }
    #pragma unroll
    for (int i = 0; i < 2; i++) {
        int kr = k0 + br + i * 8;
        int kk = (kr < K) ? kr : 0;
        int bytes = (kr < K) ? 16 : 0;
        cpa16(stage_addr + (uint32_t)(128 * SA + (br + i * 8) * SB + bc) * 4,
              B + (size_t)kk * N + n0b + bc, bytes);
    }
}

__global__ void __launch_bounds__(256, 2)
mma_gemm(const float* __restrict__ A, const float* __restrict__ B,
         const float* __restrict__ bias, float* __restrict__ C,
         int M, int N, int K, int act)
{
    extern __shared__ uint32_t dynsm[];
    uint32_t smem_u = (uint32_t)__cvta_generic_to_shared(dynsm);

    int tid = threadIdx.x, warp = tid >> 5, lane = tid & 31;
    int grp = lane >> 2, qid = lane & 3;
    int m0b = blockIdx.y * 128, n0b = blockIdx.x * 128;
    int wm = warp >> 2, wn = warp & 3;
    int m0 = wm * 64, n0 = wn * 32;

    int ar = tid >> 2, ac = (tid & 3) * 4;
    int br = tid >> 5, bc = (tid & 31) * 4;

    float acc[4][4][4];
    #pragma unroll
    for (int mt = 0; mt < 4; mt++)
        #pragma unroll
        for (int nt = 0; nt < 4; nt++)
            #pragma unroll
            for (int e = 0; e < 4; e++) acc[mt][nt][e] = 0.f;

    int ktiles = (K + 15) / 16;

    gm_issue(A, B, M, N, K, m0b, n0b, 0, smem_u, ar, ac, br, bc);
    CP_COMMIT();
    if (ktiles > 1)
        gm_issue(A, B, M, N, K, m0b, n0b, 1, smem_u + GSTAGE * 4, ar, ac, br, bc);
    CP_COMMIT();

    for (int kt = 0; kt < ktiles; kt++) {
        CP_WAIT(1);
        __syncthreads();
        if (kt + 2 < ktiles) {
            int s = (kt + 2) % 3;
            gm_issue(A, B, M, N, K, m0b, n0b, kt + 2, smem_u + (uint32_t)s * GSTAGE * 4,
                     ar, ac, br, bc);
        }
        CP_COMMIT();

        const uint32_t* As = dynsm + (kt % 3) * GSTAGE;
        const uint32_t* Bs = As + 128 * SA;
        #pragma unroll
        for (int kg = 0; kg < 2; kg++) {
            int kb = kg * 8 + qid;
            uint32_t af[4][4], bf[4][2];
            #pragma unroll
            for (int mt = 0; mt < 4; mt++) {
                int r = m0 + mt * 16 + grp;
                af[mt][0] = f2t(__uint_as_float(As[r * SA + kb]));
                af[mt][1] = f2t(__uint_as_float(As[(r + 8) * SA + kb]));
                af[mt][2] = f2t(__uint_as_float(As[r * SA + kb + 4]));
                af[mt][3] = f2t(__uint_as_float(As[(r + 8) * SA + kb + 4]));
            }
            #pragma unroll
            for (int nt = 0; nt < 4; nt++) {
                int c = n0 + nt * 8 + grp;
                bf[nt][0] = f2t(__uint_as_float(Bs[kb * SB + c]));
                bf[nt][1] = f2t(__uint_as_float(Bs[(kb + 4) * SB + c]));
            }
            #pragma unroll
            for (int mt = 0; mt < 4; mt++)
                #pragma unroll
                for (int nt = 0; nt < 4; nt++)
                    mma_tf32(acc[mt][nt], af[mt], bf[nt]);
        }
    }

    #pragma unroll
    for (int mt = 0; mt < 4; mt++) {
        int r0 = m0b + m0 + mt * 16 + grp;
        #pragma unroll
        for (int nt = 0; nt < 4; nt++) {
            int c0 = n0b + n0 + nt * 8 + qid * 2;
            float b0v = bias[c0], b1v = bias[c0 + 1];
            if (r0 < M) {
                float o0 = acc[mt][nt][0] + b0v, o1 = acc[mt][nt][1] + b1v;
                if (act) { o0 = gelu_f(o0); o1 = gelu_f(o1); }
                float2 o; o.x = o0; o.y = o1;
                *(float2*)(C + (size_t)r0 * N + c0) = o;
            }
            if (r0 + 8 < M) {
                float o0 = acc[mt][nt][2] + b0v, o1 = acc[mt][nt][3] + b1v;
                if (act) { o0 = gelu_f(o0); o1 = gelu_f(o1); }
                float2 o; o.x = o0; o.y = o1;
                *(float2*)(C + (size_t)(r0 + 8) * N + c0) = o;
            }
        }
    }
}

// ---------------- skinny GEMM for M=8: C[M,1024] = A@B + bias, opt gelu -------------
// grid (1024/128, M), block 128
__global__ void skinny_mm(const float* __restrict__ A, const float* __restrict__ B,
                          const float* __restrict__ bias, float* __restrict__ C, int act)
{
    __shared__ float As[1024];
    int tid = threadIdx.x;
    int m = blockIdx.y;
    int n = blockIdx.x * 128 + tid;
    ((float4*)As)[tid]       = ((const float4*)(A + (size_t)m * 1024))[tid];
    ((float4*)As)[tid + 128] = ((const float4*)(A + (size_t)m * 1024))[tid + 128];
    __syncthreads();
    float a0 = 0.f, a1 = 0.f, a2 = 0.f, a3 = 0.f;
    #pragma unroll 4
    for (int k = 0; k < 1024; k += 4) {
        a0 += As[k + 0] * B[(size_t)(k + 0) * 1024 + n];
        a1 += As[k + 1] * B[(size_t)(k + 1) * 1024 + n];
        a2 += As[k + 2] * B[(size_t)(k + 2) * 1024 + n];
        a3 += As[k + 3] * B[(size_t)(k + 3) * 1024 + n];
    }
    float o = (a0 + a1) + (a2 + a3) + bias[n];
    if (act) o = gelu_f(o);
    C[(size_t)m * 1024 + n] = o;
}

// ---------------- pack adjacency into bitmask; grid (NT, BB), block 128 -------------
__global__ void pack_adj(const int* __restrict__ adj)
{
    __shared__ uint32_t w[32];
    int tid = threadIdx.x;
    int b = blockIdx.y, n = blockIdx.x;
    if (tid < 32) w[tid] = 0;
    __syncthreads();
    const int4* row = (const int4*)(adj + ((size_t)(b * NT + n)) * NT);
    int4 v0 = row[tid * 2], v1 = row[tid * 2 + 1];
    uint32_t nib = 0;
    nib |= (v0.x > 0) ? 1u : 0u;
    nib |= (v0.y > 0) ? 2u : 0u;
    nib |= (v0.z > 0) ? 4u : 0u;
    nib |= (v0.w > 0) ? 8u : 0u;
    nib |= (v1.x > 0) ? 16u : 0u;
    nib |= (v1.y > 0) ? 32u : 0u;
    nib |= (v1.z > 0) ? 64u : 0u;
    nib |= (v1.w > 0) ? 128u : 0u;
    atomicOr(&w[tid >> 2], nib << ((tid & 3) * 8));
    __syncthreads();
    if (tid < 32) g_adjbits[((size_t)(b * NT + n)) * 32 + tid] = w[tid];
}

// ---------------- LayerNorm in-place over rows of length DH; grid = rows ------------
__global__ void ln_rows(float* __restrict__ X, const float* __restrict__ g,
                        const float* __restrict__ b)
{
    int r = blockIdx.x;
    float4* xr = (float4*)(X + (size_t)r * DH);
    float4 v = xr[threadIdx.x];
    float sum = block_reduce_sum(v.x + v.y + v.z + v.w);
    float mean = sum * (1.f / DH);
    float dx = v.x - mean, dy = v.y - mean, dz = v.z - mean, dw = v.w - mean;
    float sq = block_reduce_sum(dx * dx + dy * dy + dz * dz + dw * dw);
    float inv = rsqrtf(sq * (1.f / DH) + 1e-5f);
    float4 gg = ((const float4*)g)[threadIdx.x];
    float4 bv = ((const float4*)b)[threadIdx.x];
    v.x = dx * inv * gg.x + bv.x;
    v.y = dy * inv * gg.y + bv.y;
    v.z = dz * inv * gg.z + bv.z;
    v.w = dw * inv * gg.w + bv.w;
    xr[threadIdx.x] = v;
}

// ---------------- residual + LN: x = LN(x + ao); grid = B*NT rows -------------------
__global__ void resid_ln(const float* __restrict__ g, const float* __restrict__ b)
{
    int r = blockIdx.x;
    float4* xr = (float4*)(g_x + (size_t)r * DH);
    const float4* ar = (const float4*)(g_ao + (size_t)r * DH);
    float4 v = xr[threadIdx.x];
    float4 a = ar[threadIdx.x];
    v.x += a.x; v.y += a.y; v.z += a.z; v.w += a.w;
    float sum = block_reduce_sum(v.x + v.y + v.z + v.w);
    float mean = sum * (1.f / DH);
    float dx = v.x - mean, dy = v.y - mean, dz = v.z - mean, dw = v.w - mean;
    float sq = block_reduce_sum(dx * dx + dy * dy + dz * dz + dw * dw);
    float inv = rsqrtf(sq * (1.f / DH) + 1e-5f);
    float4 gg = ((const float4*)g)[threadIdx.x];
    float4 bv = ((const float4*)b)[threadIdx.x];
    v.x = dx * inv * gg.x + bv.x;
    v.y = dy * inv * gg.y + bv.y;
    v.z = dz * inv * gg.z + bv.z;
    v.w = dw * inv * gg.w + bv.w;
    xr[threadIdx.x] = v;
}

// ---------------- text masked mean pool; grid (DH/128, B), block 128 ----------------
__global__ void text_pool(const int* __restrict__ ids, const int* __restrict__ mask,
                          const float* __restrict__ emb)
{
    int b = blockIdx.y;
    int d = blockIdx.x * 128 + threadIdx.x;
    float acc = 0.f, cnt = 0.f;
    for (int l = 0; l < LQ; l++) {
        float m = (float)mask[b * LQ + l];
        int id = ids[b * LQ + l];
        acc += m * emb[(size_t)id * DH + d];
        cnt += m;
    }
    g_pool[b * DH + d] = acc / fmaxf(cnt, 1.f);
}

// ---------------- build x = concat(vis, q, kg) + type_emb[types]; grid (NT, B) ------
__global__ void pack_x(const int* __restrict__ types, const float* __restrict__ type_emb)
{
    int b = blockIdx.y, n = blockIdx.x;
    const float* src;
    if (n < NV)       src = g_vis + ((size_t)(b * NV + n)) * DH;
    else if (n == NV) src = g_q + (size_t)b * DH;
    else              src = g_kg + ((size_t)(b * NKG + (n - NV - 1))) * DH;
    int ty = types[b * NT + n];
    float4 v = ((const float4*)src)[threadIdx.x];
    float4 te = ((const float4*)(type_emb + (size_t)ty * DH))[threadIdx.x];
    v.x += te.x; v.y += te.y; v.z += te.z; v.w += te.w;
    ((float4*)(g_x + ((size_t)(b * NT + n)) * DH))[threadIdx.x] = v;
}

// ---------------- per-node s/t attention terms + factored exponentials --------------
__global__ void st_kernel(const float* __restrict__ a_src, const float* __restrict__ a_dst)
{
    int b = blockIdx.y, n = blockIdx.x;
    int h = threadIdx.x >> 5, lane = threadIdx.x & 31;
    const float4* hr = (const float4*)(g_h + ((size_t)(b * NT + n)) * DH + h * DHD);
    const float4* as = (const float4*)(a_src + h * DHD);
    const float4* ad = (const float4*)(a_dst + h * DHD);
    float4 hv = hr[lane];
    float4 av = as[lane];
    float4 dv = ad[lane];
    float s = hv.x * av.x + hv.y * av.y + hv.z * av.z + hv.w * av.w;
    float t = hv.x * dv.x + hv.y * dv.y + hv.z * dv.z + hv.w * dv.w;
    #pragma unroll
    for (int o = 16; o > 0; o >>= 1) {
        s += __shfl_down_sync(0xffffffffu, s, o);
        t += __shfl_down_sync(0xffffffffu, t, o);
    }
    if (lane == 0) {
        int idx = (b * NT + n) * NH + h;
        g_s[idx] = s;
        g_t[idx] = t;
        g_e1s[idx] = __expf(s);
        g_e2s[idx] = __expf(0.2f * s);
        g_e1t[idx] = __expf(t);
        g_e2t[idx] = __expf(0.2f * t);
    }
}

// ---------------- fused GAT attention + aggregation via tf32 MMA --------------------
// grid (NT/128, NH, B), block 256. out[128 x 128] = normalize(P) @ H.
// dyn smem (u32): Ps[2][128*36] | Hs[2][32*136] | tall[1024] | e1all[1024]
//                 | e2all[1024] | rs2[256] | invs[128]
#define GAT_SMEM_U32 (2 * 128 * PS_STRIDE + 2 * 32 * HS_STRIDE + 3 * 1024 + 256 + 128)

__global__ void __launch_bounds__(256, 2)
gat_attn_mma()
{
    extern __shared__ uint32_t dyn[];
    uint32_t smem_u = (uint32_t)__cvta_generic_to_shared(dyn);
    uint32_t* Ps0 = dyn;
    uint32_t* Hs0 = dyn + 2 * 128 * PS_STRIDE;
    float* tall  = (float*)(Hs0 + 2 * 32 * HS_STRIDE);
    float* e1all = tall + 1024;
    float* e2all = e1all + 1024;
    float* rs2   = e2all + 1024;
    float* invs  = rs2 + 256;
    const uint32_t hs_u_base = smem_u + (uint32_t)(2 * 128 * PS_STRIDE) * 4;

    int b = blockIdx.z, h = blockIdx.y, i0 = blockIdx.x * 128;
    int tid = threadIdx.x, warp = tid >> 5, lane = tid & 31;
    int grp = lane >> 2, qid = lane & 3;
    int wm = warp >> 2, wn = warp & 3;
    int m0 = wm * 64, n0 = wn * 32;
    int pi = tid >> 1, jh = (tid & 1) * 16;

    // preload t / e1t / e2t for all 1024 neighbors of this (b,h)
    #pragma unroll
    for (int it = 0; it < 4; it++) {
        int n = tid + it * 256;
        int ix = (b * NT + n) * NH + h;
        tall[n]  = g_t[ix];
        e1all[n] = g_e1t[ix];
        e2all[n] = g_e2t[ix];
    }
    int sidx = (b * NT + i0 + pi) * NH + h;
    float s_i = g_s[sidx], e1i = g_e1s[sidx], e2i = g_e2s[sidx];

    float acc[4][4][4];
    #pragma unroll
    for (int mt = 0; mt < 4; mt++)
        #pragma unroll
        for (int nt = 0; nt < 4; nt++)
            #pragma unroll
            for (int e = 0; e < 4; e++) acc[mt][nt][e] = 0.f;
    float rsum = 0.f;

    const uint32_t* arow = g_adjbits + ((size_t)(b * NT + i0 + pi)) * 32;
    int hr = tid >> 5, hc4 = tid & 31;  // for H tile cp.async: rows hr, hr+8, ... (it*8)

    // prologue: issue H tile 0
    #pragma unroll
    for (int it = 0; it < 4; it++) {
        int r = hr + it * 8;
        cpa16(hs_u_base + (uint32_t)(r * HS_STRIDE + hc4 * 4) * 4,
              g_h + ((size_t)(b * NT + 0 + r)) * DH + h * DHD + hc4 * 4, 16);
    }
    CP_COMMIT();
    uint32_t adjw = arow[0];

    __syncthreads();  // tall/e1all/e2all ready

    for (int t = 0; t < 32; t++) {
        int cur = t & 1;
        int j0 = t * 32;
        uint32_t* Ps = Ps0 + cur * 128 * PS_STRIDE;
        uint32_t* Hs = Hs0 + cur * 32 * HS_STRIDE;

        CP_WAIT(0);  // own portion of Hs[cur] resident

        // compute P tile entries (factored exp trick) + rowsum, store tf32
        #pragma unroll
        for (int q = 0; q < 4; q++) {
            uint4 pu;
            uint32_t* pp = (uint32_t*)&pu;
            #pragma unroll
            for (int e = 0; e < 4; e++) {
                int jl = jh + q * 4 + e;      // local j within tile (0..31)
                int jj = j0 + jl;
                float u = s_i + tall[jj];
                float p = 0.f;
                if ((adjw >> jl) & 1u) p = (u > 0.f) ? e1i * e1all[jj] : e2i * e2all[jj];
                uint32_t pb = f2t(p);
                pp[e] = pb;
                rsum += __uint_as_float(pb);
            }
            *(uint4*)(Ps + pi * PS_STRIDE + jh + q * 4) = pu;
        }
        __syncthreads();  // Hs[cur]+Ps[cur] visible; all warps done with [cur^1] buffers

        if (t < 31) {
            uint32_t hb = hs_u_base + (uint32_t)((cur ^ 1) * 32 * HS_STRIDE) * 4;
            #pragma unroll
            for (int it = 0; it < 4; it++) {
                int r = hr + it * 8;
                cpa16(hb + (uint32_t)(r * HS_STRIDE + hc4 * 4) * 4,
                      g_h + ((size_t)(b * NT + j0 + 32 + r)) * DH + h * DHD + hc4 * 4, 16);
            }
            CP_COMMIT();
            adjw = arow[t + 1];
        }

        // MMA: 4 k-groups of 8
        #pragma unroll
        for (int kg = 0; kg < 4; kg++) {
            int kb = kg * 8 + qid;
            uint32_t af[4][4], bf[4][2];
            #pragma unroll
            for (int mt = 0; mt < 4; mt++) {
                int r = m0 + mt * 16 + grp;
                af[mt][0] = Ps[r * PS_STRIDE + kb];
                af[mt][1] = Ps[(r + 8) * PS_STRIDE + kb];
                af[mt][2] = Ps[r * PS_STRIDE + kb + 4];
                af[mt][3] = Ps[(r + 8) * PS_STRIDE + kb + 4];
            }
            #pragma unroll
            for (int nt = 0; nt < 4; nt++) {
                int c = n0 + nt * 8 + grp;
                bf[nt][0] = f2t(__uint_as_float(Hs[kb * HS_STRIDE + c]));
                bf[nt][1] = f2t(__uint_as_float(Hs[(kb + 4) * HS_STRIDE + c]));
            }
            #pragma unroll
            for (int mt = 0; mt < 4; mt++)
                #pragma unroll
                for (int nt = 0; nt < 4; nt++)
                    mma_tf32(acc[mt][nt], af[mt], bf[nt]);
        }
    }

    rs2[pi * 2 + (tid & 1)] = rsum;
    __syncthreads();
    if (tid < 128) {
        float r = rs2[tid * 2] + rs2[tid * 2 + 1];
        invs[tid] = (r > 0.f) ? (1.f / r) : 0.f;
    }
    __syncthreads();

    #pragma unroll
    for (int mt = 0; mt < 4; mt++) {
        int rl = m0 + mt * 16 + grp;
        float iv0 = invs[rl], iv1 = invs[rl + 8];
        size_t base0 = ((size_t)(b * NT + i0 + rl)) * DH + h * DHD;
        size_t base1 = ((size_t)(b * NT + i0 + rl + 8)) * DH + h * DHD;
        #pragma unroll
        for (int nt = 0; nt < 4; nt++) {
            int c = n0 + nt * 8 + qid * 2;
            float2 o0; o0.x = acc[mt][nt][0] * iv0; o0.y = acc[mt][nt][1] * iv0;
            float2 o1; o1.x = acc[mt][nt][2] * iv1; o1.y = acc[mt][nt][3] * iv1;
            *(float2*)(g_ao + base0 + c) = o0;
            *(float2*)(g_ao + base1 + c) = o1;
        }
    }
}

// ---------------- readout ----------------
__global__ void readout_scores(const float* __restrict__ rW, const float* __restrict__ rb)
{
    int b = blockIdx.y;
    int n = blockIdx.x * 8 + (threadIdx.x >> 5);
    int lane = threadIdx.x & 31;
    const float* xr = g_x + ((size_t)(b * NT + n)) * DH;
    float acc = 0.f;
    #pragma unroll 8
    for (int k = lane; k < DH; k += 32) acc += xr[k] * rW[k];
    #pragma unroll
    for (int o = 16; o > 0; o >>= 1) acc += __shfl_down_sync(0xffffffffu, acc, o);
    if (lane == 0) g_scores[b * NT + n] = acc + rb[0];
}

__global__ void softmax_nodes()
{
    int b = blockIdx.x;
    float4 s = ((const float4*)(g_scores + b * NT))[threadIdx.x];
    float mx = fmaxf(fmaxf(s.x, s.y), fmaxf(s.z, s.w));
    mx = block_reduce_max(mx);
    float e0 = __expf(s.x - mx), e1 = __expf(s.y - mx), e2 = __expf(s.z - mx), e3 = __expf(s.w - mx);
    float sum = block_reduce_sum(e0 + e1 + e2 + e3);
    float inv = 1.f / sum;
    float4 o; o.x = e0 * inv; o.y = e1 * inv; o.z = e2 * inv; o.w = e3 * inv;
    ((float4*)(g_w + b * NT))[threadIdx.x] = o;
}

__global__ void weighted_sum()
{
    int b = blockIdx.y;
    int d = blockIdx.x * 256 + threadIdx.x;
    const float* w = g_w + b * NT;
    const float* x = g_x + (size_t)b * NT * DH + d;
    float a0 = 0.f, a1 = 0.f, a2 = 0.f, a3 = 0.f;
    for (int n = 0; n < NT; n += 4) {
        a0 += w[n + 0] * x[(size_t)(n + 0) * DH];
        a1 += w[n + 1] * x[(size_t)(n + 1) * DH];
        a2 += w[n + 2] * x[(size_t)(n + 2) * DH];
        a3 += w[n + 3] * x[(size_t)(n + 3) * DH];
    }
    g_gvec[b * DH + d] = (a0 + a1) + (a2 + a3);
}

__global__ void final_logit(const float* __restrict__ W2, const float* __restrict__ b2,
                            float* __restrict__ out)
{
    int b = blockIdx.x;
    float4 h = ((const float4*)(g_hid + (size_t)b * DH))[threadIdx.x];
    float4 w = ((const float4*)W2)[threadIdx.x];
    float total = block_reduce_sum(h.x * w.x + h.y * w.y + h.z * w.z + h.w * w.w);
    if (threadIdx.x == 0) out[b] = total + b2[0];
}

// ---------------- launch ----------------
extern "C" void kernel_launch(void* const* d_in, const int* in_sizes, int n_in,
                              void* d_out, int out_size)
{
    const float* visual   = (const float*)d_in[0];
    const int*   qids     = (const int*)d_in[1];
    const int*   qmask    = (const int*)d_in[2];
    const float* kgf      = (const float*)d_in[3];
    const int*   adj      = (const int*)d_in[4];
    const int*   ntypes   = (const int*)d_in[5];
    const float* vis_W    = (const float*)d_in[6];
    const float* vis_b    = (const float*)d_in[7];
    const float* vis_ln_g = (const float*)d_in[8];
    const float* vis_ln_b = (const float*)d_in[9];
    const float* tok_emb  = (const float*)d_in[10];
    const float* q_W      = (const float*)d_in[11];
    const float* q_b      = (const float*)d_in[12];
    const float* q_ln_g   = (const float*)d_in[13];
    const float* q_ln_b   = (const float*)d_in[14];
    const float* kg_W     = (const float*)d_in[15];
    const float* kg_b     = (const float*)d_in[16];
    const float* kg_ln_g  = (const float*)d_in[17];
    const float* kg_ln_b  = (const float*)d_in[18];
    const float* type_emb = (const float*)d_in[19];
    const float* gat_W    = (const float*)d_in[20];
    const float* gat_b    = (const float*)d_in[21];
    const float* a_src    = (const float*)d_in[22];
    const float* a_dst    = (const float*)d_in[23];
    const float* gat_ln_g = (const float*)d_in[24];
    const float* gat_ln_b = (const float*)d_in[25];
    const float* rW       = (const float*)d_in[26];
    const float* rb       = (const float*)d_in[27];
    const float* cs_W1    = (const float*)d_in[28];
    const float* cs_b1    = (const float*)d_in[29];
    const float* cs_W2    = (const float*)d_in[30];
    const float* cs_b2    = (const float*)d_in[31];
    float* out = (float*)d_out;

    float *p_vis, *p_pool, *p_q, *p_kg, *p_x, *p_h, *p_g, *p_hid;
    cudaGetSymbolAddress((void**)&p_vis,  g_vis);
    cudaGetSymbolAddress((void**)&p_pool, g_pool);
    cudaGetSymbolAddress((void**)&p_q,    g_q);
    cudaGetSymbolAddress((void**)&p_kg,   g_kg);
    cudaGetSymbolAddress((void**)&p_x,    g_x);
    cudaGetSymbolAddress((void**)&p_h,    g_h);
    cudaGetSymbolAddress((void**)&p_g,    g_gvec);
    cudaGetSymbolAddress((void**)&p_hid,  g_hid);

    const int GAT_SMEM_BYTES = GAT_SMEM_U32 * 4;
    cudaFuncSetAttribute(gat_attn_mma, cudaFuncAttributeMaxDynamicSharedMemorySize,
                         GAT_SMEM_BYTES);
    cudaFuncSetAttribute(mma_gemm, cudaFuncAttributeMaxDynamicSharedMemorySize,
                         GEMM_SMEM_BYTES);

    // adjacency bitmask (used by all GAT layers)
    pack_adj<<<dim3(NT, BB), 128>>>(adj);

    // 1. visual projection + LN
    mma_gemm<<<dim3(DH / 128, (BB * NV + 127) / 128), 256, GEMM_SMEM_BYTES>>>(
        visual, vis_W, vis_b, p_vis, BB * NV, DH, DV, 0);
    ln_rows<<<BB * NV, 256>>>(p_vis, vis_ln_g, vis_ln_b);

    // 2. text: pool -> proj -> LN
    text_pool<<<dim3(DH / 128, BB), 128>>>(qids, qmask, tok_emb);
    skinny_mm<<<dim3(DH / 128, BB), 128>>>(p_pool, q_W, q_b, p_q, 0);
    ln_rows<<<BB, 256>>>(p_q, q_ln_g, q_ln_b);

    // 3. KG projection + LN
    mma_gemm<<<dim3(DH / 128, (BB * NKG + 127) / 128), 256, GEMM_SMEM_BYTES>>>(
        kgf, kg_W, kg_b, p_kg, BB * NKG, DH, DK, 0);
    ln_rows<<<BB * NKG, 256>>>(p_kg, kg_ln_g, kg_ln_b);

    // 4-5. concat + type embeddings
    pack_x<<<dim3(NT, BB), 256>>>(ntypes, type_emb);

    // 6. GAT stack
    for (int l = 0; l < NLAYERS; l++) {
        mma_gemm<<<dim3(DH / 128, (BB * NT) / 128), 256, GEMM_SMEM_BYTES>>>(
            p_x, gat_W + (size_t)l * DH * DH, gat_b + l * DH, p_h, BB * NT, DH, DH, 0);
        st_kernel<<<dim3(NT, BB), 256>>>(a_src + l * NH * DHD, a_dst + l * NH * DHD);
        gat_attn_mma<<<dim3(NT / 128, NH, BB), 256, GAT_SMEM_BYTES>>>();
        resid_ln<<<BB * NT, 256>>>(gat_ln_g + l * DH, gat_ln_b + l * DH);
    }

    // 7. attention-pooled readout
    readout_scores<<<dim3(NT / 8, BB), 256>>>(rW, rb);
    softmax_nodes<<<BB, 256>>>();
    weighted_sum<<<dim3(DH / 256, BB), 256>>>();

    // 8. candidate scorer
    skinny_mm<<<dim3(DH / 128, BB), 128>>>(p_g, cs_W1, cs_b1, p_hid, 1);
    final_logit<<<BB, 256>>>(cs_W2, cs_b2, out);
}